// round 4
// baseline (speedup 1.0000x reference)
#include <cuda_runtime.h>

// QuantumConvLayer: probs = [c^4, c^2 s^2, s^4, s^2 c^2],
// c^2 = (1+cos x)/2, s^2 = (1-cos x)/2, x = inputs[i,0].
// HBM-bound streaming: 256MB read (every 32B input sector touched) + 256MB write.
// R3: 8x coarsening, streaming cache hints (__ldcs/__stcs), predicate-free
// fast path (N is an exact multiple of the 2048-row block tile).

#define RPT 8           // rows per thread
#define TPB 256         // threads per block
#define ROWS_PER_BLOCK (RPT * TPB)   // 2048

__device__ __forceinline__ float4 qprobs(float x)
{
    float cx = __cosf(x);
    float c2 = 0.5f + 0.5f * cx;   // cos^2(x/2)
    float s2 = 0.5f - 0.5f * cx;   // sin^2(x/2)
    float cs = c2 * s2;
    return make_float4(c2 * c2, cs, s2 * s2, cs);
}

__global__ void __launch_bounds__(TPB) qconv_kernel(
    const float* __restrict__ in,   // [N,4] row-major; only col 0 read
    float4* __restrict__ out,       // [N]
    int n)
{
    int tile = blockIdx.x * ROWS_PER_BLOCK;
    int t = threadIdx.x;

    if (tile + ROWS_PER_BLOCK <= n) {
        // Fast path: no bounds checks. Front-batch 8 independent loads.
        float x[RPT];
#pragma unroll
        for (int k = 0; k < RPT; k++)
            x[k] = __ldcs(in + 4 * (size_t)(tile + t + TPB * k));
#pragma unroll
        for (int k = 0; k < RPT; k++)
            __stcs(out + (tile + t + TPB * k), qprobs(x[k]));
    } else {
        // Tail path (not taken for N = 16M, kept for generality)
#pragma unroll
        for (int k = 0; k < RPT; k++) {
            int row = tile + t + TPB * k;
            if (row < n)
                __stcs(out + row, qprobs(__ldcs(in + 4 * (size_t)row)));
        }
    }
}

extern "C" void kernel_launch(void* const* d_in, const int* in_sizes, int n_in,
                              void* d_out, int out_size)
{
    const float* in = (const float*)d_in[0];
    float4* out = (float4*)d_out;
    int n = in_sizes[0] / 4;   // rows

    int grid = (n + ROWS_PER_BLOCK - 1) / ROWS_PER_BLOCK;
    qconv_kernel<<<grid, TPB>>>(in, out, n);
}